// round 13
// baseline (speedup 1.0000x reference)
#include <cuda_runtime.h>
#include <cuda_bf16.h>
#include <cstdint>

#define N_IMG 48
#define H1 512
#define H2 256
#define H3 128
#define NC 20

// o2 scratch, channels-last [n][y][x][ic] (~63 MB)
__device__ float g_o2[(size_t)N_IMG * H3 * H3 * NC];
// Stage-2 weight fragments, lane-linear: [ic][nt][lane] -> (bh0,bh1,bl0,bl1)
__device__ uint4 g_B2[NC * 3 * 32];

__device__ __forceinline__ int reflect_idx(int i, int S) {
    if (i < 0) return -i;
    if (i >= S) return 2 * S - 2 - i;
    return i;
}

// ---- packed f32x2 helpers --------------------------------------------------
__device__ __forceinline__ uint64_t bcast2(float v) {
    uint64_t r; asm("mov.b64 %0, {%1, %1};" : "=l"(r) : "f"(v)); return r;
}
__device__ __forceinline__ uint64_t pack2(float lo, float hi) {
    uint64_t r; asm("mov.b64 %0, {%1, %2};" : "=l"(r) : "f"(lo), "f"(hi)); return r;
}
__device__ __forceinline__ void ffma2(uint64_t& d, uint64_t a, uint64_t b) {
    asm("fma.rn.f32x2 %0, %1, %2, %0;" : "+l"(d) : "l"(a), "l"(b));
}
__device__ __forceinline__ float2 unpk(uint64_t v) {
    float2 f; asm("mov.b64 {%0, %1}, %2;" : "=f"(f.x), "=f"(f.y) : "l"(v)); return f;
}

__device__ __forceinline__ uint16_t bf16_bits(float v) {
    __nv_bfloat16 h = __float2bfloat16_rn(v);
    return *(uint16_t*)&h;
}
__device__ __forceinline__ float bf16_back(uint16_t b) {
    uint32_t u = ((uint32_t)b) << 16;
    return __uint_as_float(u);
}
// pack two floats -> bf16x2 word (hi-half = vh, lo-half = vl)
__device__ __forceinline__ uint32_t cvt_bf16x2(float vh, float vl) {
    uint32_t r;
    asm("cvt.rn.bf16x2.f32 %0, %1, %2;" : "=r"(r) : "f"(vh), "f"(vl));
    return r;
}

// mma.sync m16n8k16 row.col f32 = bf16 x bf16 + f32
__device__ __forceinline__ void mma16816(float* c, const uint32_t* a,
                                         uint32_t b0, uint32_t b1) {
    asm volatile(
        "mma.sync.aligned.m16n8k16.row.col.f32.bf16.bf16.f32 "
        "{%0,%1,%2,%3}, {%4,%5,%6,%7}, {%8,%9}, {%0,%1,%2,%3};"
        : "+f"(c[0]), "+f"(c[1]), "+f"(c[2]), "+f"(c[3])
        : "r"(a[0]), "r"(a[1]), "r"(a[2]), "r"(a[3]), "r"(b0), "r"(b1));
}

// ---------------------------------------------------------------------------
// Prep: w2 -> lane-linear bf16 hi/lo fragment table g_B2[ic][nt][lane]
// ---------------------------------------------------------------------------
__global__ void prep_kernel(const float* __restrict__ w2)
{
    int idx = blockIdx.x * 256 + threadIdx.x;
    if (idx >= NC * 3 * 32) return;
    int ic = idx / 96, rem = idx % 96;
    int nt = rem / 32, l = rem % 32;
    int g = l >> 2, q = l & 3;
    int n = nt * 8 + g;
    uint4 v = make_uint4(0, 0, 0, 0);
    if (n < NC) {
        int c0 = ic * 16 + 2 * q;
        float a0 = w2[n * 320 + c0],     a1 = w2[n * 320 + c0 + 1];
        float a8 = w2[n * 320 + c0 + 8], a9 = w2[n * 320 + c0 + 9];
        uint16_t h0 = bf16_bits(a0), h1 = bf16_bits(a1);
        uint16_t h8 = bf16_bits(a8), h9 = bf16_bits(a9);
        uint16_t l0 = bf16_bits(a0 - bf16_back(h0));
        uint16_t l1 = bf16_bits(a1 - bf16_back(h1));
        uint16_t l8 = bf16_bits(a8 - bf16_back(h8));
        uint16_t l9 = bf16_bits(a9 - bf16_back(h9));
        v.x = ((uint32_t)h1 << 16) | h0;   // bh0
        v.y = ((uint32_t)h9 << 16) | h8;   // bh1
        v.z = ((uint32_t)l1 << 16) | l0;   // bl0
        v.w = ((uint32_t)l9 << 16) | l8;   // bl1
    }
    g_B2[idx] = v;
}

// no-op: shifts ncu's captured-launch position so fused gets profiled
__global__ void dummy_kernel() {}

// ---------------------------------------------------------------------------
// Fused stage1+stage2: 256 threads, 16x16 o2 output tile, 2 CTAs/SM.
// smem: s_x[70][70] f32 (19.6KB) | o1[20][34][17] uint2 (hi,lo) (92.5KB)
// Warps 0-3: output rows 0-7; warps 4-7: rows 8-15 (two 128-px MMA groups).
// ---------------------------------------------------------------------------
#define SX_STRIDE 70
#define OFF_SX 0
#define SX_BYTES (70 * SX_STRIDE * 4)            // 19600
#define OFF_O1 SX_BYTES                           // 19600 (8B aligned)
#define O1_PLANE2 (34 * 17)                       // 578 uint2 per channel
#define O1_BYTES (NC * O1_PLANE2 * 8)             // 92480
#define FK_SMEM (OFF_O1 + O1_BYTES)               // 112080

__global__ __launch_bounds__(256, 2) void fused_mma_kernel(
    const float* __restrict__ x, const float* __restrict__ w1)
{
    extern __shared__ __align__(16) char dsm[];
    float* s_x = (float*)(dsm + OFF_SX);
    uint2* o1u2 = (uint2*)(dsm + OFF_O1);            // [oc][34 rows][17]
    __shared__ __align__(16) uint64_t w1p[16][10];   // [tap][oc-pair]

    const int n  = blockIdx.z;
    const int tid = threadIdx.x;
    const int ox0 = blockIdx.x * 16, oy0 = blockIdx.y * 16;
    const int rbase = 2 * oy0 - 1, cbase = 2 * ox0 - 1;   // o1-space origin
    const int xr0 = 4 * oy0 - 3,  xc0 = 4 * ox0 - 3;      // x-space origin

    // ---- w1 packed taps (160 entries, strided) -----------------------------
    for (int idx = tid; idx < 160; idx += 256) {
        int k = idx / 10, j = idx % 10;
        w1p[k][j] = pack2(w1[(2*j) * 16 + k], w1[(2*j + 1) * 16 + k]);
    }
    // ---- x tile (70 x 70, reflect) -----------------------------------------
    const float* __restrict__ xin = x + (size_t)n * H1 * H1;
    for (int i = tid; i < 70 * 70; i += 256) {
        int r = i / 70, c = i % 70;
        int gr = reflect_idx(xr0 + r, H1);
        int gc = reflect_idx(xc0 + c, H1);
        s_x[r * SX_STRIDE + c] = xin[(size_t)gr * H1 + gc];
    }
    __syncthreads();

    // ---- produce o1: 34 rows x 17 px-pairs, 20 ch, 2 channel-halves --------
    for (int i = tid; i < 34 * 17; i += 256) {
        int r = i / 17, cu = i % 17;
        int c0 = 2 * cu;
        int pr  = 2 * (reflect_idx(rbase + r, H2) - rbase);
        int pc0 = 2 * (reflect_idx(cbase + c0, H2) - cbase);
        int pc1 = 2 * (reflect_idx(cbase + c0 + 1, H2) - cbase);
        const int sbase = r * 17 + cu;
#pragma unroll
        for (int half = 0; half < 2; half++) {
            uint64_t acc0[5], acc1[5];
#pragma unroll
            for (int j = 0; j < 5; j++) { acc0[j] = 0ull; acc1[j] = 0ull; }
#pragma unroll
            for (int ky = 0; ky < 4; ky++) {
                const float* xr = s_x + (pr + ky) * SX_STRIDE;
                float2 A0 = *(const float2*)(xr + pc0);
                float2 B0 = *(const float2*)(xr + pc0 + 2);
                float2 A1 = *(const float2*)(xr + pc1);
                float2 B1 = *(const float2*)(xr + pc1 + 2);
                float v0[4] = {A0.x, A0.y, B0.x, B0.y};
                float v1[4] = {A1.x, A1.y, B1.x, B1.y};
#pragma unroll
                for (int kx = 0; kx < 4; kx++) {
                    uint64_t vb0 = bcast2(v0[kx]);
                    uint64_t vb1 = bcast2(v1[kx]);
                    const uint64_t* wk = w1p[ky * 4 + kx] + 5 * half;
#pragma unroll
                    for (int j = 0; j < 5; j++) {
                        ffma2(acc0[j], vb0, wk[j]);
                        ffma2(acc1[j], vb1, wk[j]);
                    }
                }
            }
#pragma unroll
            for (int j = 0; j < 5; j++) {
                int jj = 5 * half + j;
                float2 f0 = unpk(acc0[j]);   // (oc 2jj @px0, oc 2jj+1 @px0)
                float2 f1 = unpk(acc1[j]);   // same channels @px1
                // channel 2jj: word = (px1 << 16) | px0
                {
                    float va = fmaxf(f0.x, 0.f), vb = fmaxf(f1.x, 0.f);
                    uint32_t Hw = cvt_bf16x2(vb, va);
                    float ba = __uint_as_float(Hw << 16);
                    float bb = __uint_as_float(Hw & 0xFFFF0000u);
                    uint32_t Lw = cvt_bf16x2(vb - bb, va - ba);
                    o1u2[(2*jj) * O1_PLANE2 + sbase] = make_uint2(Hw, Lw);
                }
                // channel 2jj+1
                {
                    float va = fmaxf(f0.y, 0.f), vb = fmaxf(f1.y, 0.f);
                    uint32_t Hw = cvt_bf16x2(vb, va);
                    float ba = __uint_as_float(Hw << 16);
                    float bb = __uint_as_float(Hw & 0xFFFF0000u);
                    uint32_t Lw = cvt_bf16x2(vb - bb, va - ba);
                    o1u2[(2*jj + 1) * O1_PLANE2 + sbase] = make_uint2(Hw, Lw);
                }
            }
        }
    }
    __syncthreads();

    // ---- consume: mma.sync, 8 warps = 2 row-groups x (2 m-tiles x 3 nt) ----
    const int l = tid & 31, w = tid >> 5;
    const int wg = w >> 2, wl = w & 3;        // row-group, warp-in-group
    const int g = l >> 2, q = l & 3;
    const int ky0 = q >> 1;
    const int kxh = q & 1;

    float acc[2][3][4];
#pragma unroll
    for (int t = 0; t < 2; t++)
#pragma unroll
        for (int nt = 0; nt < 3; nt++)
#pragma unroll
            for (int e = 0; e < 4; e++) acc[t][nt][e] = 0.f;

#pragma unroll 2
    for (int ic = 0; ic < NC; ic++) {
        uint4 bfr[3];
#pragma unroll
        for (int nt = 0; nt < 3; nt++)
            bfr[nt] = __ldg(&g_B2[(ic * 3 + nt) * 32 + l]);

        const int pb = ic * O1_PLANE2;
        uint32_t ah[2][4], al[2][4];
#pragma unroll
        for (int t = 0; t < 2; t++) {
            int py = 8 * wg + 2 * wl + t;
            int row_lo = pb + (2 * py + ky0) * 17 + g + kxh;
            int row_hi = row_lo + 34;                 // +2 o1 rows
            uint2 U0 = o1u2[row_lo];
            uint2 U1 = o1u2[row_lo + 8];
            uint2 U2 = o1u2[row_hi];
            uint2 U3 = o1u2[row_hi + 8];
            ah[t][0] = U0.x; al[t][0] = U0.y;
            ah[t][1] = U1.x; al[t][1] = U1.y;
            ah[t][2] = U2.x; al[t][2] = U2.y;
            ah[t][3] = U3.x; al[t][3] = U3.y;
        }
#pragma unroll
        for (int nt = 0; nt < 3; nt++) {
#pragma unroll
            for (int t = 0; t < 2; t++) {
                mma16816(acc[t][nt], ah[t], bfr[nt].x, bfr[nt].y);   // hi*hi
                mma16816(acc[t][nt], ah[t], bfr[nt].z, bfr[nt].w);   // hi*lo
                mma16816(acc[t][nt], al[t], bfr[nt].x, bfr[nt].y);   // lo*hi
            }
        }
    }

    // ---- drain accumulators, relu, store channels-last ---------------------
#pragma unroll
    for (int t = 0; t < 2; t++) {
        int y = oy0 + 8 * wg + 2 * wl + t;
#pragma unroll
        for (int nt = 0; nt < 3; nt++) {
            int oc = nt * 8 + 2 * q;
            if (oc < NC) {
                float* p0 = g_o2 + (((size_t)n * H3 + y) * H3 + ox0 + g) * NC + oc;
                float* p1 = g_o2 + (((size_t)n * H3 + y) * H3 + ox0 + g + 8) * NC + oc;
                float2 v0 = make_float2(fmaxf(acc[t][nt][0], 0.f),
                                        fmaxf(acc[t][nt][1], 0.f));
                float2 v1 = make_float2(fmaxf(acc[t][nt][2], 0.f),
                                        fmaxf(acc[t][nt][3], 0.f));
                *(float2*)p0 = v0;
                *(float2*)p1 = v1;
            }
        }
    }
}

// ---------------------------------------------------------------------------
// Stage 3: 3x3 conv zero-pad-1 (20 -> 1) + ReLU
// ---------------------------------------------------------------------------
#define S3_PLANE 362   // 10*36 + 2 pad (floats)

__global__ __launch_bounds__(128) void stage3_kernel(
    const float* __restrict__ w3, float* __restrict__ out)
{
    __shared__ __align__(16) float s_in[NC * S3_PLANE];
    __shared__ __align__(16) uint64_t s_wd[NC * 9];

    const int n  = blockIdx.z;
    const int tx = threadIdx.x, ty = threadIdx.y;   // 16 x 8
    const int tid = ty * 16 + tx;
    const int ox0 = blockIdx.x * 32, oy0 = blockIdx.y * 8;

    for (int idx = tid; idx < NC * 9; idx += 128)
        s_wd[idx] = bcast2(w3[idx]);

    const float* __restrict__ ip = g_o2 + (size_t)n * H3 * H3 * NC;
    for (int i = tid; i < 340 * 5; i += 128) {
        int px = i / 5, j = i % 5;
        int r = px / 34, c = px % 34;
        int gy = oy0 - 1 + r, gx = ox0 - 1 + c;
        float4 v = make_float4(0.f, 0.f, 0.f, 0.f);
        if (gy >= 0 && gy < H3 && gx >= 0 && gx < H3)
            v = *(const float4*)(ip + ((size_t)gy * H3 + gx) * NC + 4 * j);
        float* dst = s_in + (4 * j) * S3_PLANE + r * 36 + c;
        dst[0 * S3_PLANE] = v.x;
        dst[1 * S3_PLANE] = v.y;
        dst[2 * S3_PLANE] = v.z;
        dst[3 * S3_PLANE] = v.w;
    }
    __syncthreads();

    uint64_t acc = 0ull;
#pragma unroll
    for (int ic = 0; ic < NC; ic++) {
#pragma unroll
        for (int ky = 0; ky < 3; ky++) {
            const float* vr = s_in + ic * S3_PLANE + (ty + ky) * 36 + 2 * tx;
            uint64_t vA = *(const uint64_t*)(vr);
            uint64_t vB = *(const uint64_t*)(vr + 2);
            uint64_t vM = (vA >> 32) | (vB << 32);
            ffma2(acc, vA, s_wd[ic * 9 + ky * 3 + 0]);
            ffma2(acc, vM, s_wd[ic * 9 + ky * 3 + 1]);
            ffma2(acc, vB, s_wd[ic * 9 + ky * 3 + 2]);
        }
    }

    float2 f = unpk(acc);
    float2 o = make_float2(fmaxf(f.x, 0.f), fmaxf(f.y, 0.f));
    *(float2*)(out + ((size_t)n * H3 + (oy0 + ty)) * H3 + ox0 + 2 * tx) = o;
}

// ---------------------------------------------------------------------------
extern "C" void kernel_launch(void* const* d_in, const int* in_sizes, int n_in,
                              void* d_out, int out_size)
{
    const float* x  = (const float*)d_in[0];
    const float* w1 = (const float*)d_in[1];
    const float* w2 = (const float*)d_in[2];
    const float* w3 = (const float*)d_in[3];
    float* out = (float*)d_out;

    cudaFuncSetAttribute(fused_mma_kernel,
                         cudaFuncAttributeMaxDynamicSharedMemorySize, FK_SMEM);

    prep_kernel<<<8, 256>>>(w2);
    dummy_kernel<<<1, 32>>>();
    dummy_kernel<<<1, 32>>>();
    fused_mma_kernel<<<dim3(8, 8, N_IMG), dim3(256), FK_SMEM>>>(x, w1);
    stage3_kernel<<<dim3(4, 16, N_IMG), dim3(16, 8)>>>(w3, out);
}

// round 14
// speedup vs baseline: 2.4175x; 2.4175x over previous
#include <cuda_runtime.h>
#include <cuda_bf16.h>
#include <cstdint>

#define N_IMG 48
#define H1 512
#define H2 256
#define H3 128
#define NC 20

// o2 scratch, channels-last [n][y][x][ic] (~63 MB)
__device__ float g_o2[(size_t)N_IMG * H3 * H3 * NC];
// Stage-2 weight fragments, lane-linear: [ic][nt][lane] -> (bh0,bh1,bl0,bl1)
__device__ uint4 g_B2[NC * 3 * 32];
// Stage-1 weight fragments, lane-linear: [nt][lane] (single K=16 step)
__device__ uint4 g_B1[3 * 32];

__device__ __forceinline__ int reflect_idx(int i, int S) {
    if (i < 0) return -i;
    if (i >= S) return 2 * S - 2 - i;
    return i;
}

// ---- packed f32x2 helpers (stage3) -----------------------------------------
__device__ __forceinline__ uint64_t bcast2(float v) {
    uint64_t r; asm("mov.b64 %0, {%1, %1};" : "=l"(r) : "f"(v)); return r;
}
__device__ __forceinline__ void ffma2(uint64_t& d, uint64_t a, uint64_t b) {
    asm("fma.rn.f32x2 %0, %1, %2, %0;" : "+l"(d) : "l"(a), "l"(b));
}
__device__ __forceinline__ float2 unpk(uint64_t v) {
    float2 f; asm("mov.b64 {%0, %1}, %2;" : "=f"(f.x), "=f"(f.y) : "l"(v)); return f;
}

__device__ __forceinline__ uint16_t bf16_bits(float v) {
    __nv_bfloat16 h = __float2bfloat16_rn(v);
    return *(uint16_t*)&h;
}
__device__ __forceinline__ float bf16_back(uint16_t b) {
    uint32_t u = ((uint32_t)b) << 16;
    return __uint_as_float(u);
}
// pack two floats -> bf16x2 word (hi-half = vh, lo-half = vl)
__device__ __forceinline__ uint32_t cvt_bf16x2(float vh, float vl) {
    uint32_t r;
    asm("cvt.rn.bf16x2.f32 %0, %1, %2;" : "=r"(r) : "f"(vh), "f"(vl));
    return r;
}

// mma.sync m16n8k16 row.col f32 = bf16 x bf16 + f32
__device__ __forceinline__ void mma16816(float* c, const uint32_t* a,
                                         uint32_t b0, uint32_t b1) {
    asm volatile(
        "mma.sync.aligned.m16n8k16.row.col.f32.bf16.bf16.f32 "
        "{%0,%1,%2,%3}, {%4,%5,%6,%7}, {%8,%9}, {%0,%1,%2,%3};"
        : "+f"(c[0]), "+f"(c[1]), "+f"(c[2]), "+f"(c[3])
        : "r"(a[0]), "r"(a[1]), "r"(a[2]), "r"(a[3]), "r"(b0), "r"(b1));
}

// ---------------------------------------------------------------------------
// Prep: build g_B2 (w2) and g_B1 (w1) lane-linear fragment tables
// ---------------------------------------------------------------------------
__global__ void prep_kernel(const float* __restrict__ w2,
                            const float* __restrict__ w1)
{
    int idx = blockIdx.x * 256 + threadIdx.x;
    if (idx < NC * 3 * 32) {
        int ic = idx / 96, rem = idx % 96;
        int nt = rem / 32, l = rem % 32;
        int g = l >> 2, q = l & 3;
        int n = nt * 8 + g;
        uint4 v = make_uint4(0, 0, 0, 0);
        if (n < NC) {
            int c0 = ic * 16 + 2 * q;
            float a0 = w2[n * 320 + c0],     a1 = w2[n * 320 + c0 + 1];
            float a8 = w2[n * 320 + c0 + 8], a9 = w2[n * 320 + c0 + 9];
            uint16_t h0 = bf16_bits(a0), h1 = bf16_bits(a1);
            uint16_t h8 = bf16_bits(a8), h9 = bf16_bits(a9);
            uint16_t l0 = bf16_bits(a0 - bf16_back(h0));
            uint16_t l1 = bf16_bits(a1 - bf16_back(h1));
            uint16_t l8 = bf16_bits(a8 - bf16_back(h8));
            uint16_t l9 = bf16_bits(a9 - bf16_back(h9));
            v.x = ((uint32_t)h1 << 16) | h0;
            v.y = ((uint32_t)h9 << 16) | h8;
            v.z = ((uint32_t)l1 << 16) | l0;
            v.w = ((uint32_t)l9 << 16) | l8;
        }
        g_B2[idx] = v;
    } else if (idx < NC * 3 * 32 + 96) {
        int j = idx - NC * 3 * 32;
        int nt = j / 32, l = j % 32;
        int g = l >> 2, q = l & 3;
        int n = nt * 8 + g;
        uint4 v = make_uint4(0, 0, 0, 0);
        if (n < NC) {
            int k0 = 2 * q;
            float a0 = w1[n * 16 + k0],     a1 = w1[n * 16 + k0 + 1];
            float a8 = w1[n * 16 + k0 + 8], a9 = w1[n * 16 + k0 + 9];
            uint16_t h0 = bf16_bits(a0), h1 = bf16_bits(a1);
            uint16_t h8 = bf16_bits(a8), h9 = bf16_bits(a9);
            uint16_t l0 = bf16_bits(a0 - bf16_back(h0));
            uint16_t l1 = bf16_bits(a1 - bf16_back(h1));
            uint16_t l8 = bf16_bits(a8 - bf16_back(h8));
            uint16_t l9 = bf16_bits(a9 - bf16_back(h9));
            v.x = ((uint32_t)h1 << 16) | h0;
            v.y = ((uint32_t)h9 << 16) | h8;
            v.z = ((uint32_t)l1 << 16) | l0;
            v.w = ((uint32_t)l9 << 16) | l8;
        }
        g_B1[j] = v;
    }
}

// no-op: shifts ncu's captured-launch position so fused gets profiled
__global__ void dummy_kernel() {}

// ---------------------------------------------------------------------------
// Fused stage1+stage2, both stages on mma.sync.
// CTA: 128 threads (4 warps), 16x8 o2 output px. 3 CTAs/SM.
// smem: xh/xl bf16x2-packed u32[38][36] | o1h[20][18][36] u16 | o1l same
// ---------------------------------------------------------------------------
#define XP_STRIDE 36
#define OFF_XH 0
#define XP_BYTES (38 * XP_STRIDE * 4)            // 5472
#define OFF_XL XP_BYTES                           // 5472
#define OFF_O1H (2 * XP_BYTES)                    // 10944
#define O1_PLANE16 648                            // 18*36 u16 per channel
#define O1_BYTES (NC * O1_PLANE16 * 2)            // 25920
#define OFF_O1L (OFF_O1H + O1_BYTES)              // 36864
#define FK_SMEM (OFF_O1L + O1_BYTES)              // 62784

__global__ __launch_bounds__(128, 3) void fused_mma_kernel(
    const float* __restrict__ x)
{
    extern __shared__ __align__(16) char dsm[];
    uint32_t* s_xh = (uint32_t*)(dsm + OFF_XH);      // [38][36]
    uint32_t* s_xl = (uint32_t*)(dsm + OFF_XL);
    uint16_t* o1h16 = (uint16_t*)(dsm + OFF_O1H);
    uint16_t* o1l16 = (uint16_t*)(dsm + OFF_O1L);

    const int n  = blockIdx.z;
    const int tid = threadIdx.x;
    const int ox0 = blockIdx.x * 16, oy0 = blockIdx.y * 8;
    const int rbase = 2 * oy0 - 1, cbase = 2 * ox0 - 1;   // o1-space origin
    const int xr0 = 4 * oy0 - 3,  xc0 = 4 * ox0 - 3;      // x-space origin

    const int l = tid & 31, w = tid >> 5;
    const int g = l >> 2, q = l & 3;
    const int ky0 = q >> 1, kxh = q & 1;

    // ---- x tile: reflect + bf16 hi/lo split + pair-pack (38 x 35 pairs) ----
    const float* __restrict__ xin = x + (size_t)n * H1 * H1;
    for (int i = tid; i < 38 * 35; i += 128) {
        int r = i / 35, cp = i % 35;
        int gr = reflect_idx(xr0 + r, H1);
        int gc0 = reflect_idx(xc0 + 2 * cp, H1);
        int gc1 = reflect_idx(xc0 + 2 * cp + 1, H1);
        float v0 = xin[(size_t)gr * H1 + gc0];
        float v1 = xin[(size_t)gr * H1 + gc1];
        uint32_t Hw = cvt_bf16x2(v1, v0);            // lo-half = even col
        float b0 = __uint_as_float(Hw << 16);
        float b1 = __uint_as_float(Hw & 0xFFFF0000u);
        uint32_t Lw = cvt_bf16x2(v1 - b1, v0 - b0);
        s_xh[r * XP_STRIDE + cp] = Hw;
        s_xl[r * XP_STRIDE + cp] = Lw;
    }
    __syncthreads();

    // ---- produce o1 via mma: warp-tiles of 16 px x 24 oc (612 px total) ----
    {
        uint4 b1f[3];
#pragma unroll
        for (int nt = 0; nt < 3; nt++) b1f[nt] = __ldg(&g_B1[nt * 32 + l]);

        for (int tile = w; tile < 39; tile += 4) {
            int p0 = tile * 16 + g;
            int p1 = p0 + 8;
            int pa = p0 < 611 ? p0 : 611;
            int pbx = p1 < 611 ? p1 : 611;
            int ra = pa / 34, ca = pa % 34;
            int rb = pbx / 34, cb = pbx % 34;
            int pra = 2 * (reflect_idx(rbase + ra, H2) - rbase);
            int pca = 2 * (reflect_idx(cbase + ca, H2) - cbase);
            int prb = 2 * (reflect_idx(rbase + rb, H2) - rbase);
            int pcb = 2 * (reflect_idx(cbase + cb, H2) - cbase);
            int ia0 = (pra + ky0) * XP_STRIDE + (pca >> 1) + kxh;
            int ib0 = (prb + ky0) * XP_STRIDE + (pcb >> 1) + kxh;
            uint32_t ah[4], al[4];
            ah[0] = s_xh[ia0];              al[0] = s_xl[ia0];
            ah[1] = s_xh[ib0];              al[1] = s_xl[ib0];
            ah[2] = s_xh[ia0 + 2 * XP_STRIDE]; al[2] = s_xl[ia0 + 2 * XP_STRIDE];
            ah[3] = s_xh[ib0 + 2 * XP_STRIDE]; al[3] = s_xl[ib0 + 2 * XP_STRIDE];

            float c[3][4];
#pragma unroll
            for (int nt = 0; nt < 3; nt++)
#pragma unroll
                for (int e = 0; e < 4; e++) c[nt][e] = 0.f;
#pragma unroll
            for (int nt = 0; nt < 3; nt++) {
                mma16816(c[nt], ah, b1f[nt].x, b1f[nt].y);   // hi*hi
                mma16816(c[nt], ah, b1f[nt].z, b1f[nt].w);   // hi*lo
                mma16816(c[nt], al, b1f[nt].x, b1f[nt].y);   // lo*hi
            }

            bool sa = (p0 < 612), sb = (p1 < 612);
            int sA = ra * 36 + ca, sB = rb * 36 + cb;
#pragma unroll
            for (int nt = 0; nt < 3; nt++) {
                int oc0 = nt * 8 + 2 * q;
                if (oc0 < NC) {
#pragma unroll
                    for (int e = 0; e < 4; e++) {
                        bool en = (e < 2) ? sa : sb;
                        if (!en) continue;
                        int oc = oc0 + (e & 1);
                        int s = (e < 2) ? sA : sB;
                        float vr = fmaxf(c[nt][e], 0.f);
                        uint16_t h = bf16_bits(vr);
                        uint16_t lo = bf16_bits(vr - bf16_back(h));
                        o1h16[oc * O1_PLANE16 + s] = h;
                        o1l16[oc * O1_PLANE16 + s] = lo;
                    }
                }
            }
        }
    }
    __syncthreads();

    // ---- consume: mma.sync (verbatim R11) ----------------------------------
    const uint32_t* o1h = (const uint32_t*)o1h16;   // [ic][18 rows][18 u32]
    const uint32_t* o1l = (const uint32_t*)o1l16;

    float acc[2][3][4];
#pragma unroll
    for (int t = 0; t < 2; t++)
#pragma unroll
        for (int nt = 0; nt < 3; nt++)
#pragma unroll
            for (int e = 0; e < 4; e++) acc[t][nt][e] = 0.f;

#pragma unroll 2
    for (int ic = 0; ic < NC; ic++) {
        uint4 bfr[3];
#pragma unroll
        for (int nt = 0; nt < 3; nt++)
            bfr[nt] = __ldg(&g_B2[(ic * 3 + nt) * 32 + l]);

        const int pb = ic * 324;
        uint32_t ah[2][4], al[2][4];
#pragma unroll
        for (int t = 0; t < 2; t++) {
            int py = 2 * w + t;
            int row_lo = pb + (2 * py + ky0) * 18;
            int row_hi = row_lo + 36;
            ah[t][0] = o1h[row_lo + g + kxh];
            ah[t][1] = o1h[row_lo + g + 8 + kxh];
            ah[t][2] = o1h[row_hi + g + kxh];
            ah[t][3] = o1h[row_hi + g + 8 + kxh];
            al[t][0] = o1l[row_lo + g + kxh];
            al[t][1] = o1l[row_lo + g + 8 + kxh];
            al[t][2] = o1l[row_hi + g + kxh];
            al[t][3] = o1l[row_hi + g + 8 + kxh];
        }
#pragma unroll
        for (int nt = 0; nt < 3; nt++) {
#pragma unroll
            for (int t = 0; t < 2; t++) {
                mma16816(acc[t][nt], ah[t], bfr[nt].x, bfr[nt].y);
                mma16816(acc[t][nt], ah[t], bfr[nt].z, bfr[nt].w);
                mma16816(acc[t][nt], al[t], bfr[nt].x, bfr[nt].y);
            }
        }
    }

    // ---- drain accumulators, relu, store channels-last ---------------------
#pragma unroll
    for (int t = 0; t < 2; t++) {
        int y = oy0 + 2 * w + t;
#pragma unroll
        for (int nt = 0; nt < 3; nt++) {
            int oc = nt * 8 + 2 * q;
            if (oc < NC) {
                float* p0 = g_o2 + (((size_t)n * H3 + y) * H3 + ox0 + g) * NC + oc;
                float* p1 = g_o2 + (((size_t)n * H3 + y) * H3 + ox0 + g + 8) * NC + oc;
                float2 v0 = make_float2(fmaxf(acc[t][nt][0], 0.f),
                                        fmaxf(acc[t][nt][1], 0.f));
                float2 v1 = make_float2(fmaxf(acc[t][nt][2], 0.f),
                                        fmaxf(acc[t][nt][3], 0.f));
                *(float2*)p0 = v0;
                *(float2*)p1 = v1;
            }
        }
    }
}

// ---------------------------------------------------------------------------
// Stage 3: 3x3 conv zero-pad-1 (20 -> 1) + ReLU   (verbatim R11)
// ---------------------------------------------------------------------------
#define S3_PLANE 362   // 10*36 + 2 pad (floats)

__global__ __launch_bounds__(128) void stage3_kernel(
    const float* __restrict__ w3, float* __restrict__ out)
{
    __shared__ __align__(16) float s_in[NC * S3_PLANE];
    __shared__ __align__(16) uint64_t s_wd[NC * 9];

    const int n  = blockIdx.z;
    const int tx = threadIdx.x, ty = threadIdx.y;   // 16 x 8
    const int tid = ty * 16 + tx;
    const int ox0 = blockIdx.x * 32, oy0 = blockIdx.y * 8;

    for (int idx = tid; idx < NC * 9; idx += 128)
        s_wd[idx] = bcast2(w3[idx]);

    const float* __restrict__ ip = g_o2 + (size_t)n * H3 * H3 * NC;
    for (int i = tid; i < 340 * 5; i += 128) {
        int px = i / 5, j = i % 5;
        int r = px / 34, c = px % 34;
        int gy = oy0 - 1 + r, gx = ox0 - 1 + c;
        float4 v = make_float4(0.f, 0.f, 0.f, 0.f);
        if (gy >= 0 && gy < H3 && gx >= 0 && gx < H3)
            v = *(const float4*)(ip + ((size_t)gy * H3 + gx) * NC + 4 * j);
        float* dst = s_in + (4 * j) * S3_PLANE + r * 36 + c;
        dst[0 * S3_PLANE] = v.x;
        dst[1 * S3_PLANE] = v.y;
        dst[2 * S3_PLANE] = v.z;
        dst[3 * S3_PLANE] = v.w;
    }
    __syncthreads();

    uint64_t acc = 0ull;
#pragma unroll
    for (int ic = 0; ic < NC; ic++) {
#pragma unroll
        for (int ky = 0; ky < 3; ky++) {
            const float* vr = s_in + ic * S3_PLANE + (ty + ky) * 36 + 2 * tx;
            uint64_t vA = *(const uint64_t*)(vr);
            uint64_t vB = *(const uint64_t*)(vr + 2);
            uint64_t vM = (vA >> 32) | (vB << 32);
            ffma2(acc, vA, s_wd[ic * 9 + ky * 3 + 0]);
            ffma2(acc, vM, s_wd[ic * 9 + ky * 3 + 1]);
            ffma2(acc, vB, s_wd[ic * 9 + ky * 3 + 2]);
        }
    }

    float2 f = unpk(acc);
    float2 o = make_float2(fmaxf(f.x, 0.f), fmaxf(f.y, 0.f));
    *(float2*)(out + ((size_t)n * H3 + (oy0 + ty)) * H3 + ox0 + 2 * tx) = o;
}

// ---------------------------------------------------------------------------
extern "C" void kernel_launch(void* const* d_in, const int* in_sizes, int n_in,
                              void* d_out, int out_size)
{
    const float* x  = (const float*)d_in[0];
    const float* w1 = (const float*)d_in[1];
    const float* w2 = (const float*)d_in[2];
    const float* w3 = (const float*)d_in[3];
    float* out = (float*)d_out;

    cudaFuncSetAttribute(fused_mma_kernel,
                         cudaFuncAttributeMaxDynamicSharedMemorySize, FK_SMEM);

    prep_kernel<<<8, 256>>>(w2, w1);
    dummy_kernel<<<1, 32>>>();
    dummy_kernel<<<1, 32>>>();
    fused_mma_kernel<<<dim3(8, 16, N_IMG), dim3(128), FK_SMEM>>>(x);
    stage3_kernel<<<dim3(4, 16, N_IMG), dim3(16, 8)>>>(w3, out);
}

// round 15
// speedup vs baseline: 2.6545x; 1.0980x over previous
#include <cuda_runtime.h>
#include <cuda_bf16.h>
#include <cstdint>

#define N_IMG 48
#define H1 512
#define H2 256
#define H3 128
#define NC 20

// o2 scratch, channels-last [n][y][x][ic] (~63 MB)
__device__ float g_o2[(size_t)N_IMG * H3 * H3 * NC];
// Stage-2 weight fragments, lane-linear: [ic][nt][lane] -> (bh0,bh1,bl0,bl1)
__device__ uint4 g_B2[NC * 3 * 32];
// Stage-1 weight fragments, lane-linear: [nt][lane] (single K=16 step)
__device__ uint4 g_B1[3 * 32];

__device__ __forceinline__ int reflect_idx(int i, int S) {
    if (i < 0) return -i;
    if (i >= S) return 2 * S - 2 - i;
    return i;
}

// ---- packed f32x2 helpers (stage3) -----------------------------------------
__device__ __forceinline__ uint64_t bcast2(float v) {
    uint64_t r; asm("mov.b64 %0, {%1, %1};" : "=l"(r) : "f"(v)); return r;
}
__device__ __forceinline__ void ffma2(uint64_t& d, uint64_t a, uint64_t b) {
    asm("fma.rn.f32x2 %0, %1, %2, %0;" : "+l"(d) : "l"(a), "l"(b));
}
__device__ __forceinline__ float2 unpk(uint64_t v) {
    float2 f; asm("mov.b64 {%0, %1}, %2;" : "=f"(f.x), "=f"(f.y) : "l"(v)); return f;
}

__device__ __forceinline__ uint16_t bf16_bits(float v) {
    __nv_bfloat16 h = __float2bfloat16_rn(v);
    return *(uint16_t*)&h;
}
__device__ __forceinline__ float bf16_back(uint16_t b) {
    uint32_t u = ((uint32_t)b) << 16;
    return __uint_as_float(u);
}
// pack two floats -> bf16x2 word (hi-half = vh, lo-half = vl)
__device__ __forceinline__ uint32_t cvt_bf16x2(float vh, float vl) {
    uint32_t r;
    asm("cvt.rn.bf16x2.f32 %0, %1, %2;" : "=r"(r) : "f"(vh), "f"(vl));
    return r;
}

// mma.sync m16n8k16 row.col f32 = bf16 x bf16 + f32
__device__ __forceinline__ void mma16816(float* c, const uint32_t* a,
                                         uint32_t b0, uint32_t b1) {
    asm volatile(
        "mma.sync.aligned.m16n8k16.row.col.f32.bf16.bf16.f32 "
        "{%0,%1,%2,%3}, {%4,%5,%6,%7}, {%8,%9}, {%0,%1,%2,%3};"
        : "+f"(c[0]), "+f"(c[1]), "+f"(c[2]), "+f"(c[3])
        : "r"(a[0]), "r"(a[1]), "r"(a[2]), "r"(a[3]), "r"(b0), "r"(b1));
}

// ---------------------------------------------------------------------------
// Prep: build g_B2 (w2) and g_B1 (w1) lane-linear fragment tables
// ---------------------------------------------------------------------------
__global__ void prep_kernel(const float* __restrict__ w2,
                            const float* __restrict__ w1)
{
    int idx = blockIdx.x * 256 + threadIdx.x;
    if (idx < NC * 3 * 32) {
        int ic = idx / 96, rem = idx % 96;
        int nt = rem / 32, l = rem % 32;
        int g = l >> 2, q = l & 3;
        int n = nt * 8 + g;
        uint4 v = make_uint4(0, 0, 0, 0);
        if (n < NC) {
            int c0 = ic * 16 + 2 * q;
            float a0 = w2[n * 320 + c0],     a1 = w2[n * 320 + c0 + 1];
            float a8 = w2[n * 320 + c0 + 8], a9 = w2[n * 320 + c0 + 9];
            uint16_t h0 = bf16_bits(a0), h1 = bf16_bits(a1);
            uint16_t h8 = bf16_bits(a8), h9 = bf16_bits(a9);
            uint16_t l0 = bf16_bits(a0 - bf16_back(h0));
            uint16_t l1 = bf16_bits(a1 - bf16_back(h1));
            uint16_t l8 = bf16_bits(a8 - bf16_back(h8));
            uint16_t l9 = bf16_bits(a9 - bf16_back(h9));
            v.x = ((uint32_t)h1 << 16) | h0;
            v.y = ((uint32_t)h9 << 16) | h8;
            v.z = ((uint32_t)l1 << 16) | l0;
            v.w = ((uint32_t)l9 << 16) | l8;
        }
        g_B2[idx] = v;
    } else if (idx < NC * 3 * 32 + 96) {
        int j = idx - NC * 3 * 32;
        int nt = j / 32, l = j % 32;
        int g = l >> 2, q = l & 3;
        int n = nt * 8 + g;
        uint4 v = make_uint4(0, 0, 0, 0);
        if (n < NC) {
            int k0 = 2 * q;
            float a0 = w1[n * 16 + k0],     a1 = w1[n * 16 + k0 + 1];
            float a8 = w1[n * 16 + k0 + 8], a9 = w1[n * 16 + k0 + 9];
            uint16_t h0 = bf16_bits(a0), h1 = bf16_bits(a1);
            uint16_t h8 = bf16_bits(a8), h9 = bf16_bits(a9);
            uint16_t l0 = bf16_bits(a0 - bf16_back(h0));
            uint16_t l1 = bf16_bits(a1 - bf16_back(h1));
            uint16_t l8 = bf16_bits(a8 - bf16_back(h8));
            uint16_t l9 = bf16_bits(a9 - bf16_back(h9));
            v.x = ((uint32_t)h1 << 16) | h0;
            v.y = ((uint32_t)h9 << 16) | h8;
            v.z = ((uint32_t)l1 << 16) | l0;
            v.w = ((uint32_t)l9 << 16) | l8;
        }
        g_B1[j] = v;
    }
}

// no-op: shifts ncu's captured-launch position so fused gets profiled
__global__ void dummy_kernel() {}

// ---------------------------------------------------------------------------
// Fused stage1+stage2, both stages on mma.sync.
// CTA: 128 threads (4 warps), 16x8 o2 output px. 3 CTAs/SM.
// Produce m-row remap: row g -> px 2*(tile*8+g), row g+8 -> px +1, so each
// lane owns a pixel PAIR -> packed bf16x2 epilogue with STS.32 pair-words.
// smem: xh/xl bf16x2-packed u32[38][36] | o1h[20][18][18] u32 | o1l same
// ---------------------------------------------------------------------------
#define XP_STRIDE 36
#define OFF_XH 0
#define XP_BYTES (38 * XP_STRIDE * 4)            // 5472
#define OFF_XL XP_BYTES                           // 5472
#define OFF_O1H (2 * XP_BYTES)                    // 10944
#define O1_PLANE32 324                            // 18 rows * 18 u32 per ch
#define O1_BYTES (NC * O1_PLANE32 * 4)            // 25920
#define OFF_O1L (OFF_O1H + O1_BYTES)              // 36864
#define FK_SMEM (OFF_O1L + O1_BYTES)              // 62784

__global__ __launch_bounds__(128, 3) void fused_mma_kernel(
    const float* __restrict__ x)
{
    extern __shared__ __align__(16) char dsm[];
    uint32_t* s_xh = (uint32_t*)(dsm + OFF_XH);      // [38][36]
    uint32_t* s_xl = (uint32_t*)(dsm + OFF_XL);
    uint32_t* o1h = (uint32_t*)(dsm + OFF_O1H);      // [oc][18][18] px-pair words
    uint32_t* o1l = (uint32_t*)(dsm + OFF_O1L);

    const int n  = blockIdx.z;
    const int tid = threadIdx.x;
    const int ox0 = blockIdx.x * 16, oy0 = blockIdx.y * 8;
    const int rbase = 2 * oy0 - 1, cbase = 2 * ox0 - 1;   // o1-space origin
    const int xr0 = 4 * oy0 - 3,  xc0 = 4 * ox0 - 3;      // x-space origin

    const int l = tid & 31, w = tid >> 5;
    const int g = l >> 2, q = l & 3;
    const int ky0 = q >> 1, kxh = q & 1;

    // ---- x tile: reflect + bf16 hi/lo split + pair-pack (38 x 35 pairs) ----
    const float* __restrict__ xin = x + (size_t)n * H1 * H1;
    for (int i = tid; i < 38 * 35; i += 128) {
        int r = i / 35, cp = i % 35;
        int gr = reflect_idx(xr0 + r, H1);
        int gc0 = reflect_idx(xc0 + 2 * cp, H1);
        int gc1 = reflect_idx(xc0 + 2 * cp + 1, H1);
        float v0 = xin[(size_t)gr * H1 + gc0];
        float v1 = xin[(size_t)gr * H1 + gc1];
        uint32_t Hw = cvt_bf16x2(v1, v0);            // lo-half = even col
        float b0 = __uint_as_float(Hw << 16);
        float b1 = __uint_as_float(Hw & 0xFFFF0000u);
        uint32_t Lw = cvt_bf16x2(v1 - b1, v0 - b0);
        s_xh[r * XP_STRIDE + cp] = Hw;
        s_xl[r * XP_STRIDE + cp] = Lw;
    }
    __syncthreads();

    // ---- produce o1 via mma: 39 tiles of 8 px-pairs (306 pairs total) ------
    {
        uint4 b1f[3];
#pragma unroll
        for (int nt = 0; nt < 3; nt++) b1f[nt] = __ldg(&g_B1[nt * 32 + l]);

        for (int tile = w; tile < 39; tile += 4) {
            int pi = tile * 8 + g;                  // this lane's pixel pair
            int pic = pi < 305 ? pi : 305;          // clamp for addr safety
            int px0 = 2 * pic;                      // even -> col even, no wrap
            int ra = px0 / 34, ca = px0 % 34;       // ca even, ca+1 <= 33
            int pr  = 2 * (reflect_idx(rbase + ra, H2) - rbase);
            int pc0 = 2 * (reflect_idx(cbase + ca, H2) - cbase);
            int pc1 = 2 * (reflect_idx(cbase + ca + 1, H2) - cbase);
            int ia0 = (pr + ky0) * XP_STRIDE + (pc0 >> 1) + kxh;   // px0 k-lo
            int ib0 = (pr + ky0) * XP_STRIDE + (pc1 >> 1) + kxh;   // px1 k-lo
            uint32_t ah[4], al[4];
            ah[0] = s_xh[ia0];                 al[0] = s_xl[ia0];
            ah[1] = s_xh[ib0];                 al[1] = s_xl[ib0];
            ah[2] = s_xh[ia0 + 2 * XP_STRIDE]; al[2] = s_xl[ia0 + 2 * XP_STRIDE];
            ah[3] = s_xh[ib0 + 2 * XP_STRIDE]; al[3] = s_xl[ib0 + 2 * XP_STRIDE];

            float c[3][4];
#pragma unroll
            for (int nt = 0; nt < 3; nt++)
#pragma unroll
                for (int e = 0; e < 4; e++) c[nt][e] = 0.f;
#pragma unroll
            for (int nt = 0; nt < 3; nt++) {
                mma16816(c[nt], ah, b1f[nt].x, b1f[nt].y);   // hi*hi
                mma16816(c[nt], ah, b1f[nt].z, b1f[nt].w);   // hi*lo
                mma16816(c[nt], al, b1f[nt].x, b1f[nt].y);   // lo*hi
            }

            if (pi < 306) {
                int slot = ra * 18 + (ca >> 1);     // u32 pair-word slot
#pragma unroll
                for (int nt = 0; nt < 3; nt++) {
                    int oc0 = nt * 8 + 2 * q;
                    if (oc0 + 1 < NC) {
                        // channel oc0: c[0]@px0, c[2]@px1
                        float v0 = fmaxf(c[nt][0], 0.f);
                        float v1 = fmaxf(c[nt][2], 0.f);
                        uint32_t Hw = cvt_bf16x2(v1, v0);
                        float b0 = __uint_as_float(Hw << 16);
                        float b1 = __uint_as_float(Hw & 0xFFFF0000u);
                        uint32_t Lw = cvt_bf16x2(v1 - b1, v0 - b0);
                        o1h[oc0 * O1_PLANE32 + slot] = Hw;
                        o1l[oc0 * O1_PLANE32 + slot] = Lw;
                        // channel oc0+1: c[1]@px0, c[3]@px1
                        float u0 = fmaxf(c[nt][1], 0.f);
                        float u1 = fmaxf(c[nt][3], 0.f);
                        uint32_t Hw2 = cvt_bf16x2(u1, u0);
                        float d0 = __uint_as_float(Hw2 << 16);
                        float d1 = __uint_as_float(Hw2 & 0xFFFF0000u);
                        uint32_t Lw2 = cvt_bf16x2(u1 - d1, u0 - d0);
                        o1h[(oc0 + 1) * O1_PLANE32 + slot] = Hw2;
                        o1l[(oc0 + 1) * O1_PLANE32 + slot] = Lw2;
                    }
                }
            }
        }
    }
    __syncthreads();

    // ---- consume: mma.sync (verbatim R11/R14) ------------------------------
    float acc[2][3][4];
#pragma unroll
    for (int t = 0; t < 2; t++)
#pragma unroll
        for (int nt = 0; nt < 3; nt++)
#pragma unroll
            for (int e = 0; e < 4; e++) acc[t][nt][e] = 0.f;

#pragma unroll 2
    for (int ic = 0; ic < NC; ic++) {
        uint4 bfr[3];
#pragma unroll
        for (int nt = 0; nt < 3; nt++)
            bfr[nt] = __ldg(&g_B2[(ic * 3 + nt) * 32 + l]);

        const int pb = ic * O1_PLANE32;
        uint32_t ah[2][4], al[2][4];
#pragma unroll
        for (int t = 0; t < 2; t++) {
            int py = 2 * w + t;
            int row_lo = pb + (2 * py + ky0) * 18;
            int row_hi = row_lo + 36;
            ah[t][0] = o1h[row_lo + g + kxh];
            ah[t][1] = o1h[row_lo + g + 8 + kxh];
            ah[t][2] = o1h[row_hi + g + kxh];
            ah[t][3] = o1h[row_hi + g + 8 + kxh];
            al[t][0] = o1l[row_lo + g + kxh];
            al[t][1] = o1l[row_lo + g + 8 + kxh];
            al[t][2] = o1l[row_hi + g + kxh];
            al[t][3] = o1l[row_hi + g + 8 + kxh];
        }
#pragma unroll
        for (int nt = 0; nt < 3; nt++) {
#pragma unroll
            for (int t = 0; t < 2; t++) {
                mma16816(acc[t][nt], ah[t], bfr[nt].x, bfr[nt].y);
                mma16816(acc[t][nt], ah[t], bfr[nt].z, bfr[nt].w);
                mma16816(acc[t][nt], al[t], bfr[nt].x, bfr[nt].y);
            }
        }
    }

    // ---- drain accumulators, relu, store channels-last ---------------------
#pragma unroll
    for (int t = 0; t < 2; t++) {
        int y = oy0 + 2 * w + t;
#pragma unroll
        for (int nt = 0; nt < 3; nt++) {
            int oc = nt * 8 + 2 * q;
            if (oc < NC) {
                float* p0 = g_o2 + (((size_t)n * H3 + y) * H3 + ox0 + g) * NC + oc;
                float* p1 = g_o2 + (((size_t)n * H3 + y) * H3 + ox0 + g + 8) * NC + oc;
                float2 v0 = make_float2(fmaxf(acc[t][nt][0], 0.f),
                                        fmaxf(acc[t][nt][1], 0.f));
                float2 v1 = make_float2(fmaxf(acc[t][nt][2], 0.f),
                                        fmaxf(acc[t][nt][3], 0.f));
                *(float2*)p0 = v0;
                *(float2*)p1 = v1;
            }
        }
    }
}

// ---------------------------------------------------------------------------
// Stage 3: 3x3 conv zero-pad-1 (20 -> 1) + ReLU   (verbatim R14)
// ---------------------------------------------------------------------------
#define S3_PLANE 362   // 10*36 + 2 pad (floats)

__global__ __launch_bounds__(128) void stage3_kernel(
    const float* __restrict__ w3, float* __restrict__ out)
{
    __shared__ __align__(16) float s_in[NC * S3_PLANE];
    __shared__ __align__(16) uint64_t s_wd[NC * 9];

    const int n  = blockIdx.z;
    const int tx = threadIdx.x, ty = threadIdx.y;   // 16 x 8
    const int tid = ty * 16 + tx;
    const int ox0 = blockIdx.x * 32, oy0 = blockIdx.y * 8;

    for (int idx = tid; idx < NC * 9; idx += 128)
        s_wd[idx] = bcast2(w3[idx]);

    const float* __restrict__ ip = g_o2 + (size_t)n * H3 * H3 * NC;
    for (int i = tid; i < 340 * 5; i += 128) {
        int px = i / 5, j = i % 5;
        int r = px / 34, c = px % 34;
        int gy = oy0 - 1 + r, gx = ox0 - 1 + c;
        float4 v = make_float4(0.f, 0.f, 0.f, 0.f);
        if (gy >= 0 && gy < H3 && gx >= 0 && gx < H3)
            v = *(const float4*)(ip + ((size_t)gy * H3 + gx) * NC + 4 * j);
        float* dst = s_in + (4 * j) * S3_PLANE + r * 36 + c;
        dst[0 * S3_PLANE] = v.x;
        dst[1 * S3_PLANE] = v.y;
        dst[2 * S3_PLANE] = v.z;
        dst[3 * S3_PLANE] = v.w;
    }
    __syncthreads();

    uint64_t acc = 0ull;
#pragma unroll
    for (int ic = 0; ic < NC; ic++) {
#pragma unroll
        for (int ky = 0; ky < 3; ky++) {
            const float* vr = s_in + ic * S3_PLANE + (ty + ky) * 36 + 2 * tx;
            uint64_t vA = *(const uint64_t*)(vr);
            uint64_t vB = *(const uint64_t*)(vr + 2);
            uint64_t vM = (vA >> 32) | (vB << 32);
            ffma2(acc, vA, s_wd[ic * 9 + ky * 3 + 0]);
            ffma2(acc, vM, s_wd[ic * 9 + ky * 3 + 1]);
            ffma2(acc, vB, s_wd[ic * 9 + ky * 3 + 2]);
        }
    }

    float2 f = unpk(acc);
    float2 o = make_float2(fmaxf(f.x, 0.f), fmaxf(f.y, 0.f));
    *(float2*)(out + ((size_t)n * H3 + (oy0 + ty)) * H3 + ox0 + 2 * tx) = o;
}

// ---------------------------------------------------------------------------
extern "C" void kernel_launch(void* const* d_in, const int* in_sizes, int n_in,
                              void* d_out, int out_size)
{
    const float* x  = (const float*)d_in[0];
    const float* w1 = (const float*)d_in[1];
    const float* w2 = (const float*)d_in[2];
    const float* w3 = (const float*)d_in[3];
    float* out = (float*)d_out;

    cudaFuncSetAttribute(fused_mma_kernel,
                         cudaFuncAttributeMaxDynamicSharedMemorySize, FK_SMEM);

    prep_kernel<<<8, 256>>>(w2, w1);
    dummy_kernel<<<1, 32>>>();
    dummy_kernel<<<1, 32>>>();
    fused_mma_kernel<<<dim3(8, 16, N_IMG), dim3(128), FK_SMEM>>>(x);
    stage3_kernel<<<dim3(4, 16, N_IMG), dim3(16, 8)>>>(w3, out);
}

// round 16
// speedup vs baseline: 3.0220x; 1.1384x over previous
#include <cuda_runtime.h>
#include <cuda_bf16.h>
#include <cstdint>

#define N_IMG 48
#define H1 512
#define H2 256
#define H3 128
#define NC 20

// o2 scratch, channels-last [n][y][x][ic] (~63 MB)
__device__ float g_o2[(size_t)N_IMG * H3 * H3 * NC];
// Stage-2 weight fragments, lane-linear: [ic][nt][lane] -> (bh0,bh1,bl0,bl1)
__device__ uint4 g_B2[NC * 3 * 32];
// Stage-1 weight fragments, lane-linear: [nt][lane] (single K=16 step)
__device__ uint4 g_B1[3 * 32];

__device__ __forceinline__ int reflect_idx(int i, int S) {
    if (i < 0) return -i;
    if (i >= S) return 2 * S - 2 - i;
    return i;
}

// ---- packed f32x2 helpers (stage3) -----------------------------------------
__device__ __forceinline__ uint64_t bcast2(float v) {
    uint64_t r; asm("mov.b64 %0, {%1, %1};" : "=l"(r) : "f"(v)); return r;
}
__device__ __forceinline__ void ffma2(uint64_t& d, uint64_t a, uint64_t b) {
    asm("fma.rn.f32x2 %0, %1, %2, %0;" : "+l"(d) : "l"(a), "l"(b));
}
__device__ __forceinline__ float2 unpk(uint64_t v) {
    float2 f; asm("mov.b64 {%0, %1}, %2;" : "=f"(f.x), "=f"(f.y) : "l"(v)); return f;
}

__device__ __forceinline__ uint16_t bf16_bits(float v) {
    __nv_bfloat16 h = __float2bfloat16_rn(v);
    return *(uint16_t*)&h;
}
__device__ __forceinline__ float bf16_back(uint16_t b) {
    uint32_t u = ((uint32_t)b) << 16;
    return __uint_as_float(u);
}
// pack two floats -> bf16x2 word (hi-half = vh, lo-half = vl)
__device__ __forceinline__ uint32_t cvt_bf16x2(float vh, float vl) {
    uint32_t r;
    asm("cvt.rn.bf16x2.f32 %0, %1, %2;" : "=r"(r) : "f"(vh), "f"(vl));
    return r;
}

// mma.sync m16n8k16 row.col f32 = bf16 x bf16 + f32
__device__ __forceinline__ void mma16816(float* c, const uint32_t* a,
                                         uint32_t b0, uint32_t b1) {
    asm volatile(
        "mma.sync.aligned.m16n8k16.row.col.f32.bf16.bf16.f32 "
        "{%0,%1,%2,%3}, {%4,%5,%6,%7}, {%8,%9}, {%0,%1,%2,%3};"
        : "+f"(c[0]), "+f"(c[1]), "+f"(c[2]), "+f"(c[3])
        : "r"(a[0]), "r"(a[1]), "r"(a[2]), "r"(a[3]), "r"(b0), "r"(b1));
}

// ---------------------------------------------------------------------------
// Prep: build g_B2 (w2) and g_B1 (w1) lane-linear fragment tables
// ---------------------------------------------------------------------------
__global__ void prep_kernel(const float* __restrict__ w2,
                            const float* __restrict__ w1)
{
    int idx = blockIdx.x * 256 + threadIdx.x;
    if (idx < NC * 3 * 32) {
        int ic = idx / 96, rem = idx % 96;
        int nt = rem / 32, l = rem % 32;
        int g = l >> 2, q = l & 3;
        int n = nt * 8 + g;
        uint4 v = make_uint4(0, 0, 0, 0);
        if (n < NC) {
            int c0 = ic * 16 + 2 * q;
            float a0 = w2[n * 320 + c0],     a1 = w2[n * 320 + c0 + 1];
            float a8 = w2[n * 320 + c0 + 8], a9 = w2[n * 320 + c0 + 9];
            uint16_t h0 = bf16_bits(a0), h1 = bf16_bits(a1);
            uint16_t h8 = bf16_bits(a8), h9 = bf16_bits(a9);
            uint16_t l0 = bf16_bits(a0 - bf16_back(h0));
            uint16_t l1 = bf16_bits(a1 - bf16_back(h1));
            uint16_t l8 = bf16_bits(a8 - bf16_back(h8));
            uint16_t l9 = bf16_bits(a9 - bf16_back(h9));
            v.x = ((uint32_t)h1 << 16) | h0;
            v.y = ((uint32_t)h9 << 16) | h8;
            v.z = ((uint32_t)l1 << 16) | l0;
            v.w = ((uint32_t)l9 << 16) | l8;
        }
        g_B2[idx] = v;
    } else if (idx < NC * 3 * 32 + 96) {
        int j = idx - NC * 3 * 32;
        int nt = j / 32, l = j % 32;
        int g = l >> 2, q = l & 3;
        int n = nt * 8 + g;
        uint4 v = make_uint4(0, 0, 0, 0);
        if (n < NC) {
            int k0 = 2 * q;
            float a0 = w1[n * 16 + k0],     a1 = w1[n * 16 + k0 + 1];
            float a8 = w1[n * 16 + k0 + 8], a9 = w1[n * 16 + k0 + 9];
            uint16_t h0 = bf16_bits(a0), h1 = bf16_bits(a1);
            uint16_t h8 = bf16_bits(a8), h9 = bf16_bits(a9);
            uint16_t l0 = bf16_bits(a0 - bf16_back(h0));
            uint16_t l1 = bf16_bits(a1 - bf16_back(h1));
            uint16_t l8 = bf16_bits(a8 - bf16_back(h8));
            uint16_t l9 = bf16_bits(a9 - bf16_back(h9));
            v.x = ((uint32_t)h1 << 16) | h0;
            v.y = ((uint32_t)h9 << 16) | h8;
            v.z = ((uint32_t)l1 << 16) | l0;
            v.w = ((uint32_t)l9 << 16) | l8;
        }
        g_B1[j] = v;
    }
}

// no-op: shifts ncu's captured-launch position so fused gets profiled
__global__ void dummy_kernel() {}

// ---------------------------------------------------------------------------
// Fused stage1+stage2, both stages on mma.sync.
// CTA: 256 threads (8 warps), 16x16 o2 output px. 2 CTAs/SM (16 warps).
// smem: xh/xl u32[70][35] (19.6KB) | o1h/o1l u32[20][34][17] (92.5KB)
// ---------------------------------------------------------------------------
#define XP_STRIDE 35
#define OFF_XH 0
#define XP_BYTES (70 * XP_STRIDE * 4)            // 9800
#define OFF_XL XP_BYTES                           // 9800
#define OFF_O1H (2 * XP_BYTES)                    // 19600
#define O1_PLANE32 (34 * 17)                      // 578 u32 per channel
#define O1_BYTES (NC * O1_PLANE32 * 4)            // 46240
#define OFF_O1L (OFF_O1H + O1_BYTES)              // 65840
#define FK_SMEM (OFF_O1L + O1_BYTES)              // 112080

__global__ __launch_bounds__(256, 2) void fused_mma_kernel(
    const float* __restrict__ x)
{
    extern __shared__ __align__(16) char dsm[];
    uint32_t* s_xh = (uint32_t*)(dsm + OFF_XH);      // [70][35]
    uint32_t* s_xl = (uint32_t*)(dsm + OFF_XL);
    uint32_t* o1h = (uint32_t*)(dsm + OFF_O1H);      // [oc][34][17] pair words
    uint32_t* o1l = (uint32_t*)(dsm + OFF_O1L);

    const int n  = blockIdx.z;
    const int tid = threadIdx.x;
    const int ox0 = blockIdx.x * 16, oy0 = blockIdx.y * 16;
    const int rbase = 2 * oy0 - 1, cbase = 2 * ox0 - 1;   // o1-space origin
    const int xr0 = 4 * oy0 - 3,  xc0 = 4 * ox0 - 3;      // x-space origin

    const int l = tid & 31, w = tid >> 5;
    const int g = l >> 2, q = l & 3;
    const int ky0 = q >> 1, kxh = q & 1;

    // ---- x tile: reflect + bf16 hi/lo split + pair-pack (70 x 35 pairs) ----
    const float* __restrict__ xin = x + (size_t)n * H1 * H1;
    for (int i = tid; i < 70 * 35; i += 256) {
        int r = i / 35, cp = i % 35;
        int gr = reflect_idx(xr0 + r, H1);
        int gc0 = reflect_idx(xc0 + 2 * cp, H1);
        int gc1 = reflect_idx(xc0 + 2 * cp + 1, H1);
        float v0 = xin[(size_t)gr * H1 + gc0];
        float v1 = xin[(size_t)gr * H1 + gc1];
        uint32_t Hw = cvt_bf16x2(v1, v0);            // lo-half = even col
        float b0 = __uint_as_float(Hw << 16);
        float b1 = __uint_as_float(Hw & 0xFFFF0000u);
        uint32_t Lw = cvt_bf16x2(v1 - b1, v0 - b0);
        s_xh[r * XP_STRIDE + cp] = Hw;
        s_xl[r * XP_STRIDE + cp] = Lw;
    }
    __syncthreads();

    // ---- produce o1 via mma: 73 tiles of 8 px-pairs (578 pairs total) ------
    {
        uint4 b1f[3];
#pragma unroll
        for (int nt = 0; nt < 3; nt++) b1f[nt] = __ldg(&g_B1[nt * 32 + l]);

        for (int tile = w; tile < 73; tile += 8) {
            int pi = tile * 8 + g;                  // this lane's pixel pair
            int pic = pi < 577 ? pi : 577;          // clamp for addr safety
            int px0 = 2 * pic;                      // even -> even col in 34
            int ra = px0 / 34, ca = px0 % 34;       // ca even, ca+1 <= 33
            int pr  = 2 * (reflect_idx(rbase + ra, H2) - rbase);
            int pc0 = 2 * (reflect_idx(cbase + ca, H2) - cbase);
            int pc1 = 2 * (reflect_idx(cbase + ca + 1, H2) - cbase);
            int ia0 = (pr + ky0) * XP_STRIDE + (pc0 >> 1) + kxh;   // px0 k-lo
            int ib0 = (pr + ky0) * XP_STRIDE + (pc1 >> 1) + kxh;   // px1 k-lo
            uint32_t ah[4], al[4];
            ah[0] = s_xh[ia0];                 al[0] = s_xl[ia0];
            ah[1] = s_xh[ib0];                 al[1] = s_xl[ib0];
            ah[2] = s_xh[ia0 + 2 * XP_STRIDE]; al[2] = s_xl[ia0 + 2 * XP_STRIDE];
            ah[3] = s_xh[ib0 + 2 * XP_STRIDE]; al[3] = s_xl[ib0 + 2 * XP_STRIDE];

            float c[3][4];
#pragma unroll
            for (int nt = 0; nt < 3; nt++)
#pragma unroll
                for (int e = 0; e < 4; e++) c[nt][e] = 0.f;
#pragma unroll
            for (int nt = 0; nt < 3; nt++) {
                mma16816(c[nt], ah, b1f[nt].x, b1f[nt].y);   // hi*hi
                mma16816(c[nt], ah, b1f[nt].z, b1f[nt].w);   // hi*lo
                mma16816(c[nt], al, b1f[nt].x, b1f[nt].y);   // lo*hi
            }

            if (pi < 578) {
                int slot = ra * 17 + (ca >> 1);     // u32 pair-word slot
#pragma unroll
                for (int nt = 0; nt < 3; nt++) {
                    int oc0 = nt * 8 + 2 * q;
                    if (oc0 + 1 < NC) {
                        float v0 = fmaxf(c[nt][0], 0.f);
                        float v1 = fmaxf(c[nt][2], 0.f);
                        uint32_t Hw = cvt_bf16x2(v1, v0);
                        float b0 = __uint_as_float(Hw << 16);
                        float b1 = __uint_as_float(Hw & 0xFFFF0000u);
                        uint32_t Lw = cvt_bf16x2(v1 - b1, v0 - b0);
                        o1h[oc0 * O1_PLANE32 + slot] = Hw;
                        o1l[oc0 * O1_PLANE32 + slot] = Lw;
                        float u0 = fmaxf(c[nt][1], 0.f);
                        float u1 = fmaxf(c[nt][3], 0.f);
                        uint32_t Hw2 = cvt_bf16x2(u1, u0);
                        float d0 = __uint_as_float(Hw2 << 16);
                        float d1 = __uint_as_float(Hw2 & 0xFFFF0000u);
                        uint32_t Lw2 = cvt_bf16x2(u1 - d1, u0 - d0);
                        o1h[(oc0 + 1) * O1_PLANE32 + slot] = Hw2;
                        o1l[(oc0 + 1) * O1_PLANE32 + slot] = Lw2;
                    }
                }
            }
        }
    }
    __syncthreads();

    // ---- consume: mma.sync, 8 warps x 2 m-rows = 16 py rows ----------------
    float acc[2][3][4];
#pragma unroll
    for (int t = 0; t < 2; t++)
#pragma unroll
        for (int nt = 0; nt < 3; nt++)
#pragma unroll
            for (int e = 0; e < 4; e++) acc[t][nt][e] = 0.f;

#pragma unroll 2
    for (int ic = 0; ic < NC; ic++) {
        uint4 bfr[3];
#pragma unroll
        for (int nt = 0; nt < 3; nt++)
            bfr[nt] = __ldg(&g_B2[(ic * 3 + nt) * 32 + l]);

        const int pb = ic * O1_PLANE32;
        uint32_t ah[2][4], al[2][4];
#pragma unroll
        for (int t = 0; t < 2; t++) {
            int py = 2 * w + t;
            int row_lo = pb + (2 * py + ky0) * 17;
            int row_hi = row_lo + 34;                 // +2 o1 rows
            ah[t][0] = o1h[row_lo + g + kxh];
            ah[t][1] = o1h[row_lo + g + 8 + kxh];
            ah[t][2] = o1h[row_hi + g + kxh];
            ah[t][3] = o1h[row_hi + g + 8 + kxh];
            al[t][0] = o1l[row_lo + g + kxh];
            al[t][1] = o1l[row_lo + g + 8 + kxh];
            al[t][2] = o1l[row_hi + g + kxh];
            al[t][3] = o1l[row_hi + g + 8 + kxh];
        }
#pragma unroll
        for (int nt = 0; nt < 3; nt++) {
#pragma unroll
            for (int t = 0; t < 2; t++) {
                mma16816(acc[t][nt], ah[t], bfr[nt].x, bfr[nt].y);
                mma16816(acc[t][nt], ah[t], bfr[nt].z, bfr[nt].w);
                mma16816(acc[t][nt], al[t], bfr[nt].x, bfr[nt].y);
            }
        }
    }

    // ---- drain accumulators, relu, store channels-last ---------------------
#pragma unroll
    for (int t = 0; t < 2; t++) {
        int y = oy0 + 2 * w + t;
#pragma unroll
        for (int nt = 0; nt < 3; nt++) {
            int oc = nt * 8 + 2 * q;
            if (oc < NC) {
                float* p0 = g_o2 + (((size_t)n * H3 + y) * H3 + ox0 + g) * NC + oc;
                float* p1 = g_o2 + (((size_t)n * H3 + y) * H3 + ox0 + g + 8) * NC + oc;
                float2 v0 = make_float2(fmaxf(acc[t][nt][0], 0.f),
                                        fmaxf(acc[t][nt][1], 0.f));
                float2 v1 = make_float2(fmaxf(acc[t][nt][2], 0.f),
                                        fmaxf(acc[t][nt][3], 0.f));
                *(float2*)p0 = v0;
                *(float2*)p1 = v1;
            }
        }
    }
}

// ---------------------------------------------------------------------------
// Stage 3: 3x3 conv zero-pad-1 (20 -> 1) + ReLU   (verbatim R14/R15)
// ---------------------------------------------------------------------------
#define S3_PLANE 362   // 10*36 + 2 pad (floats)

__global__ __launch_bounds__(128) void stage3_kernel(
    const float* __restrict__ w3, float* __restrict__ out)
{
    __shared__ __align__(16) float s_in[NC * S3_PLANE];
    __shared__ __align__(16) uint64_t s_wd[NC * 9];

    const int n  = blockIdx.z;
    const int tx = threadIdx.x, ty = threadIdx.y;   // 16 x 8
    const int tid = ty * 16 + tx;
    const int ox0 = blockIdx.x * 32, oy0 = blockIdx.y * 8;

    for (int idx = tid; idx < NC * 9; idx += 128)
        s_wd[idx] = bcast2(w3[idx]);

    const float* __restrict__ ip = g_o2 + (size_t)n * H3 * H3 * NC;
    for (int i = tid; i < 340 * 5; i += 128) {
        int px = i / 5, j = i % 5;
        int r = px / 34, c = px % 34;
        int gy = oy0 - 1 + r, gx = ox0 - 1 + c;
        float4 v = make_float4(0.f, 0.f, 0.f, 0.f);
        if (gy >= 0 && gy < H3 && gx >= 0 && gx < H3)
            v = *(const float4*)(ip + ((size_t)gy * H3 + gx) * NC + 4 * j);
        float* dst = s_in + (4 * j) * S3_PLANE + r * 36 + c;
        dst[0 * S3_PLANE] = v.x;
        dst[1 * S3_PLANE] = v.y;
        dst[2 * S3_PLANE] = v.z;
        dst[3 * S3_PLANE] = v.w;
    }
    __syncthreads();

    uint64_t acc = 0ull;
#pragma unroll
    for (int ic = 0; ic < NC; ic++) {
#pragma unroll
        for (int ky = 0; ky < 3; ky++) {
            const float* vr = s_in + ic * S3_PLANE + (ty + ky) * 36 + 2 * tx;
            uint64_t vA = *(const uint64_t*)(vr);
            uint64_t vB = *(const uint64_t*)(vr + 2);
            uint64_t vM = (vA >> 32) | (vB << 32);
            ffma2(acc, vA, s_wd[ic * 9 + ky * 3 + 0]);
            ffma2(acc, vM, s_wd[ic * 9 + ky * 3 + 1]);
            ffma2(acc, vB, s_wd[ic * 9 + ky * 3 + 2]);
        }
    }

    float2 f = unpk(acc);
    float2 o = make_float2(fmaxf(f.x, 0.f), fmaxf(f.y, 0.f));
    *(float2*)(out + ((size_t)n * H3 + (oy0 + ty)) * H3 + ox0 + 2 * tx) = o;
}

// ---------------------------------------------------------------------------
extern "C" void kernel_launch(void* const* d_in, const int* in_sizes, int n_in,
                              void* d_out, int out_size)
{
    const float* x  = (const float*)d_in[0];
    const float* w1 = (const float*)d_in[1];
    const float* w2 = (const float*)d_in[2];
    const float* w3 = (const float*)d_in[3];
    float* out = (float*)d_out;

    cudaFuncSetAttribute(fused_mma_kernel,
                         cudaFuncAttributeMaxDynamicSharedMemorySize, FK_SMEM);

    prep_kernel<<<8, 256>>>(w2, w1);
    dummy_kernel<<<1, 32>>>();
    dummy_kernel<<<1, 32>>>();
    fused_mma_kernel<<<dim3(8, 8, N_IMG), dim3(256), FK_SMEM>>>(x);
    stage3_kernel<<<dim3(4, 16, N_IMG), dim3(16, 8)>>>(w3, out);
}